// round 1
// baseline (speedup 1.0000x reference)
#include <cuda_runtime.h>
#include <cuda_bf16.h>

// Problem constants (from reference): N=100000, E=3200000, F_in=128, H=25, C=40
#define MAXN 100000
#define MAXE 3200000
#define FIN  128
#define H1   25
#define C2   40

// Scratch (allocation-free rule: __device__ globals)
__device__ float g_deg [MAXN];
__device__ float g_dinv[MAXN];
__device__ float g_h1  [MAXN * H1];   // x @ W1
__device__ float g_agg1[MAXN * H1];   // scatter target, layer 1
__device__ float g_h2  [MAXN * C2];   // relu(agg1+self+b1) @ W2
__device__ int   g_is64;

// ---------------------------------------------------------------------------
// edge_index dtype detection: reference says int64, but JAX without x64 mode
// silently produces int32. If int64, every odd int32 word (high half) is 0.
__global__ void detect_kernel(const int* __restrict__ ei) {
    int all0 = 1;
    for (int k = 0; k < 64; k++)
        if (ei[2 * k + 1] != 0) { all0 = 0; break; }
    g_is64 = all0;
}

__device__ __forceinline__ long long ld_idx(const void* base, long long pos, int is64) {
    if (is64) return ((const long long*)base)[pos];
    return (long long)((const int*)base)[pos];
}

// ---------------------------------------------------------------------------
// init: deg=1 (self-loop weight), agg1=0, out(agg2)=0
__global__ void init_kernel(float* __restrict__ out, int N) {
    int i = blockIdx.x * blockDim.x + threadIdx.x;
    if (i < N)       g_deg[i]  = 1.0f;
    if (i < N * H1)  g_agg1[i] = 0.0f;
    if (i < N * C2)  out[i]    = 0.0f;
}

__global__ void degree_kernel(const void* __restrict__ ei,
                              const float* __restrict__ w, int E) {
    int e = blockIdx.x * blockDim.x + threadIdx.x;
    if (e >= E) return;
    int is64 = g_is64;
    long long d = ld_idx(ei, (long long)E + e, is64);
    atomicAdd(&g_deg[d], w[e]);
}

__global__ void dinv_kernel(int N) {
    int i = blockIdx.x * blockDim.x + threadIdx.x;
    if (i >= N) return;
    float d = g_deg[i];
    g_dinv[i] = (d > 0.0f) ? rsqrtf(d) : 0.0f;
}

// ---------------------------------------------------------------------------
// GEMM1: h1[N,25] = x[N,128] @ W1[128,25].  Tile of 32 rows per block.
#define G1_TB  256
#define G1_RPB 32
__global__ void gemm1_kernel(const float* __restrict__ x,
                             const float* __restrict__ W1, int N) {
    __shared__ float xs[G1_RPB][FIN + 1];   // +1 pad: kill r-stride bank conflicts
    __shared__ float ws[FIN * H1];
    int row0 = blockIdx.x * G1_RPB;

    for (int i = threadIdx.x; i < FIN * H1; i += G1_TB) ws[i] = W1[i];

    const float4* x4 = (const float4*)(x + (size_t)row0 * FIN);
    for (int i = threadIdx.x; i < G1_RPB * (FIN / 4); i += G1_TB) {
        int r = i >> 5;              // 32 float4 per row
        int k = (i & 31) << 2;
        if (row0 + r < N) {
            float4 v = x4[i];
            xs[r][k] = v.x; xs[r][k + 1] = v.y; xs[r][k + 2] = v.z; xs[r][k + 3] = v.w;
        }
    }
    __syncthreads();

    for (int o = threadIdx.x; o < G1_RPB * H1; o += G1_TB) {
        int r = o / H1, c = o % H1;
        if (row0 + r >= N) continue;
        float acc = 0.0f;
        #pragma unroll 16
        for (int k = 0; k < FIN; k++) acc += xs[r][k] * ws[k * H1 + c];
        g_h1[(size_t)(row0 + r) * H1 + c] = acc;
    }
}

// ---------------------------------------------------------------------------
// Layer-1 propagate: thread per edge, 25-feature loop.
// norm recomputed on the fly (dinv is 400KB, L1/L2-hot) -> no norm array pass.
__global__ void scatter1_kernel(const void* __restrict__ ei,
                                const float* __restrict__ w, int E) {
    int e = blockIdx.x * blockDim.x + threadIdx.x;
    if (e >= E) return;
    int is64 = g_is64;
    long long s = ld_idx(ei, e, is64);
    long long d = ld_idx(ei, (long long)E + e, is64);
    float nm = g_dinv[s] * w[e] * g_dinv[d];
    const float* hs = &g_h1[s * H1];
    float*       ad = &g_agg1[d * H1];
    #pragma unroll
    for (int f = 0; f < H1; f++)
        atomicAdd(&ad[f], nm * __ldg(&hs[f]));
}

// ---------------------------------------------------------------------------
// Fused: a = relu(agg1 + dinv^2*h1 + b1); h2 = a @ W2[25,40]. Thread per node.
__global__ void fuse1_kernel(const float* __restrict__ b1,
                             const float* __restrict__ W2, int N) {
    __shared__ float w2s[H1 * C2];
    __shared__ float b1s[H1];
    for (int i = threadIdx.x; i < H1 * C2; i += blockDim.x) w2s[i] = W2[i];
    if (threadIdx.x < H1) b1s[threadIdx.x] = b1[threadIdx.x];
    __syncthreads();

    int i = blockIdx.x * blockDim.x + threadIdx.x;
    if (i >= N) return;
    float dv = g_dinv[i];
    float d2 = dv * dv;

    float a[H1];
    #pragma unroll
    for (int k = 0; k < H1; k++) {
        float v = g_agg1[i * H1 + k] + d2 * g_h1[i * H1 + k] + b1s[k];
        a[k] = v > 0.0f ? v : 0.0f;
    }
    #pragma unroll
    for (int c = 0; c < C2; c++) {
        float acc = 0.0f;
        #pragma unroll
        for (int k = 0; k < H1; k++) acc += a[k] * w2s[k * C2 + c];
        g_h2[i * C2 + c] = acc;
    }
}

// ---------------------------------------------------------------------------
// Layer-2 propagate: thread per edge, 40-feature loop, scatters into d_out.
__global__ void scatter2_kernel(const void* __restrict__ ei,
                                const float* __restrict__ w,
                                float* __restrict__ out, int E) {
    int e = blockIdx.x * blockDim.x + threadIdx.x;
    if (e >= E) return;
    int is64 = g_is64;
    long long s = ld_idx(ei, e, is64);
    long long d = ld_idx(ei, (long long)E + e, is64);
    float nm = g_dinv[s] * w[e] * g_dinv[d];
    const float* hs = &g_h2[s * C2];
    float*       ad = &out[d * C2];
    #pragma unroll
    for (int f = 0; f < C2; f++)
        atomicAdd(&ad[f], nm * __ldg(&hs[f]));
}

// ---------------------------------------------------------------------------
// Final: v = agg2 + dinv^2*h2 + b2; out = v - logsumexp(v). Thread per node.
__global__ void final_kernel(float* __restrict__ out,
                             const float* __restrict__ b2, int N) {
    __shared__ float b2s[C2];
    if (threadIdx.x < C2) b2s[threadIdx.x] = b2[threadIdx.x];
    __syncthreads();

    int i = blockIdx.x * blockDim.x + threadIdx.x;
    if (i >= N) return;
    float dv = g_dinv[i];
    float d2 = dv * dv;

    float v[C2];
    float m = -3.4e38f;
    #pragma unroll
    for (int f = 0; f < C2; f++) {
        float t = out[i * C2 + f] + d2 * g_h2[i * C2 + f] + b2s[f];
        v[f] = t;
        m = fmaxf(m, t);
    }
    float ssum = 0.0f;
    #pragma unroll
    for (int f = 0; f < C2; f++) ssum += __expf(v[f] - m);
    float lse = m + logf(ssum);
    #pragma unroll
    for (int f = 0; f < C2; f++) out[i * C2 + f] = v[f] - lse;
}

// ---------------------------------------------------------------------------
extern "C" void kernel_launch(void* const* d_in, const int* in_sizes, int n_in,
                              void* d_out, int out_size) {
    const float* x  = (const float*)d_in[0];
    const void*  ei = d_in[1];
    const float* w  = (const float*)d_in[2];
    const float* W1 = (const float*)d_in[3];
    const float* b1 = (const float*)d_in[4];
    const float* W2 = (const float*)d_in[5];
    const float* b2 = (const float*)d_in[6];
    float* out = (float*)d_out;

    int E = in_sizes[2];
    int N = in_sizes[0] / FIN;

    const int TB = 256;
    int gridE  = (E + TB - 1) / TB;
    int gridN  = (N + TB - 1) / TB;
    int gridNC = (N * C2 + TB - 1) / TB;

    detect_kernel<<<1, 1>>>((const int*)ei);
    init_kernel<<<gridNC, TB>>>(out, N);
    degree_kernel<<<gridE, TB>>>(ei, w, E);
    dinv_kernel<<<gridN, TB>>>(N);
    gemm1_kernel<<<(N + G1_RPB - 1) / G1_RPB, G1_TB>>>(x, W1, N);
    scatter1_kernel<<<gridE, TB>>>(ei, w, E);
    fuse1_kernel<<<gridN, TB>>>(b1, W2, N);
    scatter2_kernel<<<gridE, TB>>>(ei, w, out, E);
    final_kernel<<<gridN, TB>>>(out, b2, N);
}

// round 3
// speedup vs baseline: 2.4434x; 2.4434x over previous
#include <cuda_runtime.h>
#include <cuda_bf16.h>

// Problem constants: N=100000, E=3200000, F_in=128, H=25, C=40
#define MAXN 100000
#define MAXE 3200000
#define FIN  128
#define H1   25
#define C2   40

// Scratch (__device__ globals — allocation-free rule)
__device__ float g_deg [MAXN];
__device__ float g_dinv[MAXN];
__device__ int   g_cnt [MAXN];        // in-degree (excl. self-loop)
__device__ int   g_row [MAXN + 1];    // CSR row offsets (by dst)
__device__ int   g_cur [MAXN];        // build cursors
__device__ int   g_csrc[MAXE];        // CSR: src index
__device__ float g_cval[MAXE];        // CSR: dinv[s]*w*dinv[d]
__device__ float g_h1  [MAXN * H1];   // x @ W1
__device__ float g_h2  [MAXN * C2];   // relu(agg1+self+b1) @ W2
__device__ int   g_is64;

// ---------------------------------------------------------------------------
// edge_index dtype detect: if int64, high words of first 64 entries are all 0.
__global__ void detect_kernel(const int* __restrict__ ei) {
    int all0 = 1;
    for (int k = 0; k < 64; k++)
        if (ei[2 * k + 1] != 0) { all0 = 0; break; }
    g_is64 = all0;
}

__device__ __forceinline__ long long ld_idx(const void* base, long long pos, int is64) {
    if (is64) return ((const long long*)base)[pos];
    return (long long)((const int*)base)[pos];
}

// ---------------------------------------------------------------------------
__global__ void init_kernel(int N) {
    int i = blockIdx.x * blockDim.x + threadIdx.x;
    if (i < N) { g_deg[i] = 1.0f; g_cnt[i] = 0; }
}

__global__ void degree_kernel(const void* __restrict__ ei,
                              const float* __restrict__ w, int E) {
    int e = blockIdx.x * blockDim.x + threadIdx.x;
    if (e >= E) return;
    int is64 = g_is64;
    long long d = ld_idx(ei, (long long)E + e, is64);
    atomicAdd(&g_deg[(int)d], w[e]);
    atomicAdd(&g_cnt[(int)d], 1);
}

__global__ void dinv_kernel(int N) {
    int i = blockIdx.x * blockDim.x + threadIdx.x;
    if (i >= N) return;
    float d = g_deg[i];
    g_dinv[i] = (d > 0.0f) ? rsqrtf(d) : 0.0f;
}

// ---------------------------------------------------------------------------
// Single-block exclusive scan of g_cnt -> g_row, g_cur.  1024 threads,
// each handles a contiguous strip; Hillis-Steele over the 1024 strip sums.
__global__ void scan_kernel(int N) {
    __shared__ int sh[1024];
    int t = threadIdx.x;
    const int CH = (N + 1023) / 1024;
    int base = t * CH;
    int s = 0;
    for (int k = 0; k < CH; k++) { int i = base + k; if (i < N) s += g_cnt[i]; }
    sh[t] = s;  __syncthreads();
    for (int off = 1; off < 1024; off <<= 1) {
        int v = (t >= off) ? sh[t - off] : 0;
        __syncthreads();
        sh[t] += v;
        __syncthreads();
    }
    int run = sh[t] - s;   // exclusive prefix
    for (int k = 0; k < CH; k++) {
        int i = base + k;
        if (i < N) { g_row[i] = run; g_cur[i] = run; run += g_cnt[i]; }
    }
    if (t == 1023) g_row[N] = run;
}

// Bucket-scatter edges into CSR slots; norm folded in here.
__global__ void build_kernel(const void* __restrict__ ei,
                             const float* __restrict__ w, int E) {
    int e = blockIdx.x * blockDim.x + threadIdx.x;
    if (e >= E) return;
    int is64 = g_is64;
    int s = (int)ld_idx(ei, e, is64);
    int d = (int)ld_idx(ei, (long long)E + e, is64);
    float nm = g_dinv[s] * w[e] * g_dinv[d];
    int pos = atomicAdd(&g_cur[d], 1);
    g_csrc[pos] = s;
    g_cval[pos] = nm;
}

// ---------------------------------------------------------------------------
// GEMM1: h1[N,25] = x[N,128] @ W1[128,25].
#define G1_TB  256
#define G1_RPB 32
__global__ void gemm1_kernel(const float* __restrict__ x,
                             const float* __restrict__ W1, int N) {
    __shared__ float xs[G1_RPB][FIN + 1];
    __shared__ float ws[FIN * H1];
    int row0 = blockIdx.x * G1_RPB;

    for (int i = threadIdx.x; i < FIN * H1; i += G1_TB) ws[i] = W1[i];

    const float4* x4 = (const float4*)(x + (size_t)row0 * FIN);
    for (int i = threadIdx.x; i < G1_RPB * (FIN / 4); i += G1_TB) {
        int r = i >> 5;
        int k = (i & 31) << 2;
        if (row0 + r < N) {
            float4 v = x4[i];
            xs[r][k] = v.x; xs[r][k+1] = v.y; xs[r][k+2] = v.z; xs[r][k+3] = v.w;
        }
    }
    __syncthreads();

    for (int o = threadIdx.x; o < G1_RPB * H1; o += G1_TB) {
        int r = o / H1, c = o % H1;
        if (row0 + r >= N) continue;
        float acc = 0.0f;
        #pragma unroll 16
        for (int k = 0; k < FIN; k++) acc += xs[r][k] * ws[k * H1 + c];
        g_h1[(size_t)(row0 + r) * H1 + c] = acc;
    }
}

// ---------------------------------------------------------------------------
// Layer-1 aggregate + self-loop + b1 + ReLU + GEMM2, all fused.
// Warp per node; lane = feature (lane<25 active for accum).
#define WPB1 8
__global__ void agg1_kernel(const float* __restrict__ b1,
                            const float* __restrict__ W2, int N) {
    __shared__ float w2s[H1 * C2];
    __shared__ float b1s[H1];
    __shared__ float sa[WPB1][H1];
    for (int i = threadIdx.x; i < H1 * C2; i += WPB1 * 32) w2s[i] = W2[i];
    if (threadIdx.x < H1) b1s[threadIdx.x] = b1[threadIdx.x];
    __syncthreads();

    int warp = threadIdx.x >> 5;
    int lane = threadIdx.x & 31;
    int i = blockIdx.x * WPB1 + warp;
    if (i >= N) return;

    float dv = g_dinv[i];
    float acc = 0.0f;
    if (lane < H1) acc = dv * dv * __ldg(&g_h1[(size_t)i * H1 + lane]);

    int j0 = g_row[i], j1 = g_row[i + 1];
    for (int j = j0; j < j1; j++) {
        int   s = __ldg(&g_csrc[j]);      // broadcast
        float v = __ldg(&g_cval[j]);      // broadcast
        if (lane < H1) acc += v * __ldg(&g_h1[(size_t)s * H1 + lane]);
    }

    if (lane < H1) {
        float a = acc + b1s[lane];
        sa[warp][lane] = a > 0.0f ? a : 0.0f;
    }
    __syncwarp();

    // GEMM2 row: each lane computes output col(s)
    const float* a = sa[warp];
    float o0 = 0.0f, o1 = 0.0f;
    #pragma unroll
    for (int k = 0; k < H1; k++) {
        float av = a[k];
        o0 += av * w2s[k * C2 + lane];
        if (lane < C2 - 32) o1 += av * w2s[k * C2 + lane + 32];
    }
    g_h2[(size_t)i * C2 + lane] = o0;
    if (lane < C2 - 32) g_h2[(size_t)i * C2 + lane + 32] = o1;
}

// ---------------------------------------------------------------------------
// Layer-2 aggregate + self-loop + b2 + log-softmax, fused. Warp per node.
// Lane holds features f=lane and (lane<8) f=lane+32.
#define WPB2 8
__global__ void agg2_kernel(float* __restrict__ out,
                            const float* __restrict__ b2, int N) {
    __shared__ float b2s[C2];
    if (threadIdx.x < C2) b2s[threadIdx.x] = b2[threadIdx.x];
    __syncthreads();

    int warp = threadIdx.x >> 5;
    int lane = threadIdx.x & 31;
    int i = blockIdx.x * WPB2 + warp;
    if (i >= N) return;

    float dv = g_dinv[i];
    float d2 = dv * dv;
    float a0 = d2 * __ldg(&g_h2[(size_t)i * C2 + lane]);
    float a1 = (lane < C2 - 32) ? d2 * __ldg(&g_h2[(size_t)i * C2 + lane + 32]) : 0.0f;

    int j0 = g_row[i], j1 = g_row[i + 1];
    for (int j = j0; j < j1; j++) {
        int   s = __ldg(&g_csrc[j]);
        float v = __ldg(&g_cval[j]);
        a0 += v * __ldg(&g_h2[(size_t)s * C2 + lane]);
        if (lane < C2 - 32) a1 += v * __ldg(&g_h2[(size_t)s * C2 + lane + 32]);
    }

    a0 += b2s[lane];
    bool has1 = (lane < C2 - 32);
    if (has1) a1 += b2s[lane + 32];

    // log-softmax over the 40 values held across the warp
    float m = fmaxf(a0, has1 ? a1 : -3.4e38f);
    #pragma unroll
    for (int off = 16; off > 0; off >>= 1)
        m = fmaxf(m, __shfl_xor_sync(0xffffffffu, m, off));
    float s = __expf(a0 - m) + (has1 ? __expf(a1 - m) : 0.0f);
    #pragma unroll
    for (int off = 16; off > 0; off >>= 1)
        s += __shfl_xor_sync(0xffffffffu, s, off);
    float lse = m + logf(s);

    out[(size_t)i * C2 + lane] = a0 - lse;
    if (has1) out[(size_t)i * C2 + lane + 32] = a1 - lse;
}

// ---------------------------------------------------------------------------
extern "C" void kernel_launch(void* const* d_in, const int* in_sizes, int n_in,
                              void* d_out, int out_size) {
    const float* x  = (const float*)d_in[0];
    const void*  ei = d_in[1];
    const float* w  = (const float*)d_in[2];
    const float* W1 = (const float*)d_in[3];
    const float* b1 = (const float*)d_in[4];
    const float* W2 = (const float*)d_in[5];
    const float* b2 = (const float*)d_in[6];
    float* out = (float*)d_out;

    int E = in_sizes[2];
    int N = in_sizes[0] / FIN;

    const int TB = 256;
    int gridE = (E + TB - 1) / TB;
    int gridN = (N + TB - 1) / TB;

    detect_kernel<<<1, 1>>>((const int*)ei);
    init_kernel<<<gridN, TB>>>(N);
    degree_kernel<<<gridE, TB>>>(ei, w, E);
    dinv_kernel<<<gridN, TB>>>(N);
    scan_kernel<<<1, 1024>>>(N);
    build_kernel<<<gridE, TB>>>(ei, w, E);
    gemm1_kernel<<<(N + G1_RPB - 1) / G1_RPB, G1_TB>>>(x, W1, N);
    agg1_kernel<<<(N + WPB1 - 1) / WPB1, WPB1 * 32>>>(b1, W2, N);
    agg2_kernel<<<(N + WPB2 - 1) / WPB2, WPB2 * 32>>>(out, b2, N);
}

// round 4
// speedup vs baseline: 4.1096x; 1.6819x over previous
#include <cuda_runtime.h>
#include <cuda_bf16.h>

// Problem constants: N=100000, E=3200000, F_in=128, H=25, C=40
#define MAXN 100000
#define MAXE 3200000
#define FIN  128
#define H1   25
#define H1P  32        // padded row pitch for h1 (128B aligned gathers)
#define C2   40
#define C2P  48        // padded row pitch for h2 (192B, 32B-aligned)

// Scratch (__device__ globals — allocation-free rule; zero-init at load)
__device__ float g_deg [MAXN];
__device__ float g_dinv[MAXN];
__device__ int   g_cnt [MAXN];
__device__ int   g_row [MAXN + 1];
__device__ int   g_cur [MAXN];
__device__ int   g_psum[128];          // per-block partial sums (<=98 used)
__device__ int   g_poff[128];
__device__ int2  g_edge[MAXE];         // {src, float_bits(norm)} interleaved
__device__ float g_h1p [MAXN * H1P];   // x @ W1, padded (pad cols stay 0)
__device__ float g_h2p [MAXN * C2P];   // layer-2 input, padded
__device__ int   g_is64;

// ---------------------------------------------------------------------------
// dtype detect: if int64, high words of first 64 entries are all 0.
__global__ void detect_kernel(const int* __restrict__ ei) {
    int all0 = 1;
    for (int k = 0; k < 64; k++)
        if (ei[2 * k + 1] != 0) { all0 = 0; break; }
    g_is64 = all0;
}

__device__ __forceinline__ int ld_node(const int* __restrict__ ei32,
                                       long long pos, int is64) {
    return ei32[is64 ? (pos << 1) : pos];   // little-endian low word
}

// ---------------------------------------------------------------------------
__global__ void init_kernel(int N) {
    int i = blockIdx.x * blockDim.x + threadIdx.x;
    if (i < N) { g_deg[i] = 1.0f; g_cnt[i] = 0; }
}

__global__ void degree_kernel(const int* __restrict__ ei32,
                              const float* __restrict__ w, int E) {
    int e = blockIdx.x * blockDim.x + threadIdx.x;
    if (e >= E) return;
    int is64 = g_is64;
    int d = ld_node(ei32, (long long)E + e, is64);
    atomicAdd(&g_deg[d], w[e]);
    atomicAdd(&g_cnt[d], 1);
}

__global__ void dinv_kernel(int N) {
    int i = blockIdx.x * blockDim.x + threadIdx.x;
    if (i >= N) return;
    float d = g_deg[i];
    g_dinv[i] = (d > 0.0f) ? rsqrtf(d) : 0.0f;
}

// ---------------------------------------------------------------------------
// 3-phase scan of g_cnt -> g_row (exclusive), g_cur copy, g_row[N]=E.
__global__ void scan_local(int N) {
    __shared__ int sh[1024];
    int i = blockIdx.x * 1024 + threadIdx.x;
    int v = (i < N) ? g_cnt[i] : 0;
    sh[threadIdx.x] = v;
    __syncthreads();
    int acc = v;
    for (int off = 1; off < 1024; off <<= 1) {
        int p = (threadIdx.x >= off) ? sh[threadIdx.x - off] : 0;
        __syncthreads();
        acc += p;
        sh[threadIdx.x] = acc;
        __syncthreads();
    }
    if (i < N) g_row[i] = acc - v;                 // exclusive within block
    if (threadIdx.x == 1023) g_psum[blockIdx.x] = acc;
}

__global__ void scan_tops(int NB, int N, int E) {
    __shared__ int sh[128];
    int t = threadIdx.x;
    int v = (t < NB) ? g_psum[t] : 0;
    sh[t] = v;
    __syncthreads();
    int acc = v;
    for (int off = 1; off < 128; off <<= 1) {
        int p = (t >= off) ? sh[t - off] : 0;
        __syncthreads();
        acc += p;
        sh[t] = acc;
        __syncthreads();
    }
    if (t < NB) g_poff[t] = acc - v;
    if (t == 0) g_row[N] = E;
}

__global__ void scan_add(int N) {
    int i = blockIdx.x * blockDim.x + threadIdx.x;
    if (i >= N) return;
    int r = g_row[i] + g_poff[i >> 10];
    g_row[i] = r;
    g_cur[i] = r;
}

// Bucket-scatter edges into CSR slots; norm folded; single 8B store.
__global__ void build_kernel(const int* __restrict__ ei32,
                             const float* __restrict__ w, int E) {
    int e = blockIdx.x * blockDim.x + threadIdx.x;
    if (e >= E) return;
    int is64 = g_is64;
    int s = ld_node(ei32, e, is64);
    int d = ld_node(ei32, (long long)E + e, is64);
    float nm = g_dinv[s] * w[e] * g_dinv[d];
    int pos = atomicAdd(&g_cur[d], 1);
    g_edge[pos] = make_int2(s, __float_as_int(nm));
}

// ---------------------------------------------------------------------------
// GEMM1: h1p[N,32] = x[N,128] @ W1[128,25] (cols 25..31 untouched -> stay 0).
// Register-blocked 4 rows x 5 cols per thread; W1 in smem; x via float4 LDG.
#define G1_TB   320            // 64 rowGroups x 5 colGroups
#define G1_RPB  256            // rows per block
__global__ void gemm1_kernel(const float* __restrict__ x,
                             const float* __restrict__ W1, int N) {
    __shared__ float ws[FIN * H1];
    for (int i = threadIdx.x; i < FIN * H1; i += G1_TB) ws[i] = W1[i];
    __syncthreads();

    int rowGroup = threadIdx.x / 5;          // 0..63
    int colGroup = threadIdx.x % 5;          // 0..4
    int r0 = blockIdx.x * G1_RPB + rowGroup * 4;
    int c0 = colGroup * 5;

    float acc[4][5];
    #pragma unroll
    for (int a = 0; a < 4; a++)
        #pragma unroll
        for (int b = 0; b < 5; b++) acc[a][b] = 0.0f;

    #pragma unroll 4
    for (int kb = 0; kb < FIN / 4; kb++) {
        float xr[4][4];
        #pragma unroll
        for (int a = 0; a < 4; a++) {
            int r = r0 + a;
            float4 v = (r < N) ? __ldg((const float4*)(x + (size_t)r * FIN) + kb)
                               : make_float4(0.f, 0.f, 0.f, 0.f);
            xr[a][0] = v.x; xr[a][1] = v.y; xr[a][2] = v.z; xr[a][3] = v.w;
        }
        #pragma unroll
        for (int t = 0; t < 4; t++) {
            int k = kb * 4 + t;
            float wv[5];
            #pragma unroll
            for (int b = 0; b < 5; b++) wv[b] = ws[k * H1 + c0 + b];
            #pragma unroll
            for (int a = 0; a < 4; a++)
                #pragma unroll
                for (int b = 0; b < 5; b++) acc[a][b] += xr[a][t] * wv[b];
        }
    }

    #pragma unroll
    for (int a = 0; a < 4; a++) {
        int r = r0 + a;
        if (r >= N) break;
        #pragma unroll
        for (int b = 0; b < 5; b++)
            g_h1p[(size_t)r * H1P + c0 + b] = acc[a][b];
    }
}

// ---------------------------------------------------------------------------
// Layer-1: CSR gather-aggregate + self-loop + b1 + ReLU + GEMM2 -> h2p.
// Warp per node, lane = feature. Gathers are 128B coalesced.
#define WPB1 8
__global__ void agg1_kernel(const float* __restrict__ b1,
                            const float* __restrict__ W2, int N) {
    __shared__ float w2s[H1 * C2];
    __shared__ float b1s[H1];
    __shared__ float sa[WPB1][H1];
    for (int i = threadIdx.x; i < H1 * C2; i += WPB1 * 32) w2s[i] = W2[i];
    if (threadIdx.x < H1) b1s[threadIdx.x] = b1[threadIdx.x];
    __syncthreads();

    int warp = threadIdx.x >> 5;
    int lane = threadIdx.x & 31;
    int i = blockIdx.x * WPB1 + warp;
    if (i >= N) return;

    float dv = g_dinv[i];
    float acc = dv * dv * __ldg(&g_h1p[(size_t)i * H1P + lane]);

    int j0 = g_row[i], j1 = g_row[i + 1];
    for (int j = j0; j < j1; j++) {
        int2  pr = __ldg(&g_edge[j]);                       // broadcast 8B
        float v  = __int_as_float(pr.y);
        acc += v * __ldg(&g_h1p[(size_t)pr.x * H1P + lane]); // 128B coalesced
    }

    if (lane < H1) {
        float a = acc + b1s[lane];
        sa[warp][lane] = a > 0.0f ? a : 0.0f;
    }
    __syncwarp();

    const float* a = sa[warp];
    float o0 = 0.0f, o1 = 0.0f;
    #pragma unroll
    for (int k = 0; k < H1; k++) {
        float av = a[k];
        o0 += av * w2s[k * C2 + lane];
        if (lane < C2 - 32) o1 += av * w2s[k * C2 + lane + 32];
    }
    g_h2p[(size_t)i * C2P + lane] = o0;
    if (lane < C2 - 32) g_h2p[(size_t)i * C2P + 32 + lane] = o1;
}

// ---------------------------------------------------------------------------
// Layer-2: CSR gather-aggregate + self-loop + b2 + log-softmax -> out.
#define WPB2 8
__global__ void agg2_kernel(float* __restrict__ out,
                            const float* __restrict__ b2, int N) {
    __shared__ float b2s[C2];
    if (threadIdx.x < C2) b2s[threadIdx.x] = b2[threadIdx.x];
    __syncthreads();

    int warp = threadIdx.x >> 5;
    int lane = threadIdx.x & 31;
    int i = blockIdx.x * WPB2 + warp;
    if (i >= N) return;

    bool has1 = (lane < C2 - 32);
    float dv = g_dinv[i];
    float d2 = dv * dv;
    float a0 = d2 * __ldg(&g_h2p[(size_t)i * C2P + lane]);
    float a1 = has1 ? d2 * __ldg(&g_h2p[(size_t)i * C2P + 32 + lane]) : 0.0f;

    int j0 = g_row[i], j1 = g_row[i + 1];
    for (int j = j0; j < j1; j++) {
        int2  pr = __ldg(&g_edge[j]);
        float v  = __int_as_float(pr.y);
        const float* hs = &g_h2p[(size_t)pr.x * C2P];
        a0 += v * __ldg(hs + lane);                         // 128B coalesced
        if (has1) a1 += v * __ldg(hs + 32 + lane);          // 32B sector
    }

    a0 += b2s[lane];
    if (has1) a1 += b2s[lane + 32];

    float m = fmaxf(a0, has1 ? a1 : -3.4e38f);
    #pragma unroll
    for (int off = 16; off > 0; off >>= 1)
        m = fmaxf(m, __shfl_xor_sync(0xffffffffu, m, off));
    float s = __expf(a0 - m) + (has1 ? __expf(a1 - m) : 0.0f);
    #pragma unroll
    for (int off = 16; off > 0; off >>= 1)
        s += __shfl_xor_sync(0xffffffffu, s, off);
    float lse = m + logf(s);

    out[(size_t)i * C2 + lane] = a0 - lse;
    if (has1) out[(size_t)i * C2 + 32 + lane] = a1 - lse;
}

// ---------------------------------------------------------------------------
extern "C" void kernel_launch(void* const* d_in, const int* in_sizes, int n_in,
                              void* d_out, int out_size) {
    const float* x    = (const float*)d_in[0];
    const int*   ei32 = (const int*)d_in[1];
    const float* w    = (const float*)d_in[2];
    const float* W1   = (const float*)d_in[3];
    const float* b1   = (const float*)d_in[4];
    const float* W2   = (const float*)d_in[5];
    const float* b2   = (const float*)d_in[6];
    float* out = (float*)d_out;

    int E = in_sizes[2];
    int N = in_sizes[0] / FIN;

    const int TB = 256;
    int gridE = (E + TB - 1) / TB;
    int gridN = (N + TB - 1) / TB;
    int NB    = (N + 1023) / 1024;

    detect_kernel<<<1, 1>>>(ei32);
    init_kernel<<<gridN, TB>>>(N);
    degree_kernel<<<gridE, TB>>>(ei32, w, E);
    dinv_kernel<<<gridN, TB>>>(N);
    scan_local<<<NB, 1024>>>(N);
    scan_tops<<<1, 128>>>(NB, N, E);
    scan_add<<<gridN, TB>>>(N);
    build_kernel<<<gridE, TB>>>(ei32, w, E);
    gemm1_kernel<<<(N + G1_RPB - 1) / G1_RPB, G1_TB>>>(x, W1, N);
    agg1_kernel<<<(N + WPB1 - 1) / WPB1, WPB1 * 32>>>(b1, W2, N);
    agg2_kernel<<<(N + WPB2 - 1) / WPB2, WPB2 * 32>>>(out, b2, N);
}